// round 2
// baseline (speedup 1.0000x reference)
#include <cuda_runtime.h>
#include <cstdint>

// ---------------- problem constants ----------------
#define L_Q   13343
#define BLMAX 26686          // B=2 * L_Q
#define CDIM  256

__constant__ int c_HW[5]    = {100, 50, 25, 13, 7};      // square levels: H==W
__constant__ int c_start[5] = {0, 10000, 12500, 13125, 13294};

// ---------------- scratch (static device globals; no allocs) ----------------
__device__ float g_value[(size_t)BLMAX * 256];
__device__ float g_off  [(size_t)BLMAX * 320];
__device__ float g_attn [(size_t)BLMAX * 160];
__device__ float g_acc  [(size_t)BLMAX * 256];
__device__ float g_src2 [(size_t)BLMAX * 256];
__device__ float g_x    [(size_t)BLMAX * 256];
__device__ float g_h    [(size_t)BLMAX * 2048];
__device__ float g_y    [(size_t)BLMAX * 256];

// ---------------- fp32 tiled GEMM: C = act(A (+A2)) @ W + bias ----------------
// BM=BN=128, BK=8, 256 threads, 8x8 register tile per thread.
#define GBM 128
#define GBN 128
#define GBK 8

template<bool ADD_A, bool RELU>
__global__ __launch_bounds__(256, 2)
void gemm_kernel(const float* __restrict__ A, const float* __restrict__ A2,
                 const float* __restrict__ W, const float* __restrict__ bias,
                 float* __restrict__ C, int M, int N, int K)
{
    __shared__ float As[GBK][GBM];
    __shared__ float Bs[GBK][GBN];

    const int tid = threadIdx.x;
    const int bm  = blockIdx.y * GBM;
    const int bn  = blockIdx.x * GBN;
    const int tx  = tid & 15;       // 16 cols of threads
    const int ty  = tid >> 4;       // 16 rows of threads

    // A tile loader: 128 rows x 8 k, float4 per thread (2 threads / row)
    const int arow = tid >> 1;
    const int acol = (tid & 1) * 4;
    // B tile loader: 8 k-rows x 128 cols, float4 per thread (32 threads / row)
    const int brow = tid >> 5;
    const int bcol = (tid & 31) * 4;

    float acc[8][8];
#pragma unroll
    for (int i = 0; i < 8; i++)
#pragma unroll
        for (int j = 0; j < 8; j++) acc[i][j] = 0.f;

    const bool aval = (bm + arow) < M;
    const bool bval = (bn + bcol) < N;

    const float* Aptr  = A  + (size_t)(bm + arow) * K + acol;
    const float* A2ptr = nullptr;
    if (ADD_A) A2ptr = A2 + (size_t)(bm + arow) * K + acol;
    const float* Wptr  = W + (size_t)brow * N + (bn + bcol);

    for (int k0 = 0; k0 < K; k0 += GBK) {
        float4 av = make_float4(0.f, 0.f, 0.f, 0.f);
        if (aval) {
            av = *(const float4*)(Aptr + k0);
            if (ADD_A) {
                float4 a2 = *(const float4*)(A2ptr + k0);
                av.x += a2.x; av.y += a2.y; av.z += a2.z; av.w += a2.w;
            }
        }
        float4 bv = make_float4(0.f, 0.f, 0.f, 0.f);
        if (bval) bv = *(const float4*)(Wptr + (size_t)k0 * N);

        __syncthreads();
        As[acol + 0][arow] = av.x;
        As[acol + 1][arow] = av.y;
        As[acol + 2][arow] = av.z;
        As[acol + 3][arow] = av.w;
        *(float4*)&Bs[brow][bcol] = bv;
        __syncthreads();

#pragma unroll
        for (int k = 0; k < GBK; k++) {
            float4 a0 = *(const float4*)&As[k][ty * 8];
            float4 a1 = *(const float4*)&As[k][ty * 8 + 4];
            float4 b0 = *(const float4*)&Bs[k][tx * 8];
            float4 b1 = *(const float4*)&Bs[k][tx * 8 + 4];
            float aa[8] = {a0.x, a0.y, a0.z, a0.w, a1.x, a1.y, a1.z, a1.w};
            float bb[8] = {b0.x, b0.y, b0.z, b0.w, b1.x, b1.y, b1.z, b1.w};
#pragma unroll
            for (int i = 0; i < 8; i++)
#pragma unroll
                for (int j = 0; j < 8; j++)
                    acc[i][j] = fmaf(aa[i], bb[j], acc[i][j]);
        }
    }

    // epilogue: +bias, optional relu
#pragma unroll
    for (int i = 0; i < 8; i++) {
        int row = bm + ty * 8 + i;
        if (row >= M) continue;
#pragma unroll
        for (int j = 0; j < 8; j += 4) {
            int col = bn + tx * 8 + j;
            if (col < N) {
                float4 o;
                o.x = acc[i][j + 0] + bias[col + 0];
                o.y = acc[i][j + 1] + bias[col + 1];
                o.z = acc[i][j + 2] + bias[col + 2];
                o.w = acc[i][j + 3] + bias[col + 3];
                if (RELU) {
                    o.x = fmaxf(o.x, 0.f); o.y = fmaxf(o.y, 0.f);
                    o.z = fmaxf(o.z, 0.f); o.w = fmaxf(o.w, 0.f);
                }
                *(float4*)&C[(size_t)row * N + col] = o;
            }
        }
    }
}

// ---------------- deformable sampling ----------------
// One block per query (b,q). 8 warps = 8 heads; 32 lanes = 32 channels (DH).
__global__ __launch_bounds__(256)
void sample_kernel(const float* __restrict__ value,   // [B, L, 256]
                   const float* __restrict__ ref,     // [B, L, 5, 2]
                   const float* __restrict__ off,     // [B*L, 320]
                   const float* __restrict__ logits,  // [B*L, 160]
                   float* __restrict__ acc_out)       // [B*L, 256]
{
    const int i = blockIdx.x;            // query row in [0, B*L)
    const int b = i / L_Q;
    const int tid  = threadIdx.x;
    const int h    = tid >> 5;
    const int lane = tid & 31;

    __shared__ float s_off[320];
    __shared__ float s_log[160];
    __shared__ float s_ref[10];

    for (int t = tid; t < 320; t += 256) s_off[t] = off[(size_t)i * 320 + t];
    if (tid < 160) s_log[tid] = logits[(size_t)i * 160 + tid];
    if (tid < 10)  s_ref[tid] = ref[(size_t)i * 10 + tid];
    __syncthreads();

    // softmax stats over this head's 20 logits (lane-uniform)
    float m = -1e30f;
#pragma unroll
    for (int p = 0; p < 20; p++) m = fmaxf(m, s_log[h * 20 + p]);
    float ssum = 0.f;
#pragma unroll
    for (int p = 0; p < 20; p++) ssum += expf(s_log[h * 20 + p] - m);
    const float inv = 1.0f / ssum;

    float a = 0.f;
    const float* vbase = value + (size_t)b * L_Q * 256 + h * 32 + lane;

#pragma unroll
    for (int l = 0; l < 5; l++) {
        const int Hs = c_HW[l], Ws = c_HW[l];
        const float* vlvl = vbase + (size_t)c_start[l] * 256;
        const float rx = s_ref[l * 2 + 0];
        const float ry = s_ref[l * 2 + 1];
#pragma unroll
        for (int p = 0; p < 4; p++) {
            const float ox = s_off[h * 40 + l * 8 + p * 2 + 0];
            const float oy = s_off[h * 40 + l * 8 + p * 2 + 1];
            const float w  = expf(s_log[h * 20 + l * 4 + p] - m) * inv;

            // match reference op order: loc = ref + off/norm; p = loc*size - 0.5
            const float locx = rx + ox / (float)Ws;
            const float locy = ry + oy / (float)Hs;
            const float px = locx * (float)Ws - 0.5f;
            const float py = locy * (float)Hs - 0.5f;

            const float x0f = floorf(px), y0f = floorf(py);
            const float lx = px - x0f, ly = py - y0f;
            const int x0 = (int)x0f, y0 = (int)y0f;
            const int x1 = x0 + 1,  y1 = y0 + 1;

            const bool vx0 = (x0 >= 0) & (x0 < Ws);
            const bool vx1 = (x1 >= 0) & (x1 < Ws);
            const bool vy0 = (y0 >= 0) & (y0 < Hs);
            const bool vy1 = (y1 >= 0) & (y1 < Hs);

            float s = 0.f;
            if (vx0 & vy0) s += (1.f - lx) * (1.f - ly) * vlvl[(size_t)(y0 * Ws + x0) * 256];
            if (vx1 & vy0) s += lx * (1.f - ly)         * vlvl[(size_t)(y0 * Ws + x1) * 256];
            if (vx0 & vy1) s += (1.f - lx) * ly         * vlvl[(size_t)(y1 * Ws + x0) * 256];
            if (vx1 & vy1) s += lx * ly                 * vlvl[(size_t)(y1 * Ws + x1) * 256];

            a = fmaf(w, s, a);
        }
    }
    acc_out[(size_t)i * 256 + tid] = a;
}

// ---------------- fused add + layernorm: out = LN(a+b)*g + beta ----------------
// 8 warps per block, one row (256 cols) per warp.
__global__ __launch_bounds__(256)
void add_ln_kernel(const float* __restrict__ a, const float* __restrict__ b,
                   const float* __restrict__ g, const float* __restrict__ be,
                   float* __restrict__ out, int M)
{
    const int warp = threadIdx.x >> 5;
    const int lane = threadIdx.x & 31;
    const int row  = blockIdx.x * 8 + warp;
    if (row >= M) return;

    const float* ar = a + (size_t)row * 256;
    const float* br = b + (size_t)row * 256;

    float4 v0 = *(const float4*)(ar + lane * 4);
    float4 v1 = *(const float4*)(ar + 128 + lane * 4);
    float4 w0 = *(const float4*)(br + lane * 4);
    float4 w1 = *(const float4*)(br + 128 + lane * 4);

    float v[8];
    v[0] = v0.x + w0.x; v[1] = v0.y + w0.y; v[2] = v0.z + w0.z; v[3] = v0.w + w0.w;
    v[4] = v1.x + w1.x; v[5] = v1.y + w1.y; v[6] = v1.z + w1.z; v[7] = v1.w + w1.w;

    float s = 0.f, sq = 0.f;
#pragma unroll
    for (int i = 0; i < 8; i++) { s += v[i]; sq = fmaf(v[i], v[i], sq); }
#pragma unroll
    for (int o = 16; o; o >>= 1) {
        s  += __shfl_xor_sync(0xffffffffu, s,  o);
        sq += __shfl_xor_sync(0xffffffffu, sq, o);
    }
    const float mean = s * (1.f / 256.f);
    const float var  = sq * (1.f / 256.f) - mean * mean;
    const float inv  = rsqrtf(var + 1e-5f);

    float* orow = out + (size_t)row * 256;
#pragma unroll
    for (int half = 0; half < 2; half++) {
        int c = half * 128 + lane * 4;
        float4 o;
        float* vv = v + half * 4;
        o.x = (vv[0] - mean) * inv * g[c + 0] + be[c + 0];
        o.y = (vv[1] - mean) * inv * g[c + 1] + be[c + 1];
        o.z = (vv[2] - mean) * inv * g[c + 2] + be[c + 2];
        o.w = (vv[3] - mean) * inv * g[c + 3] + be[c + 3];
        *(float4*)&orow[c] = o;
    }
}

// ---------------- launch ----------------
static inline dim3 gemm_grid(int M, int N) {
    return dim3((N + GBN - 1) / GBN, (M + GBM - 1) / GBM);
}

extern "C" void kernel_launch(void* const* d_in, const int* in_sizes, int n_in,
                              void* d_out, int out_size)
{
    const float* src  = (const float*)d_in[0];
    const float* pos  = (const float*)d_in[1];
    const float* ref  = (const float*)d_in[2];
    const float* wv   = (const float*)d_in[3];
    const float* bv   = (const float*)d_in[4];
    const float* wo   = (const float*)d_in[5];
    const float* bo   = (const float*)d_in[6];
    const float* wa   = (const float*)d_in[7];
    const float* ba   = (const float*)d_in[8];
    const float* wout = (const float*)d_in[9];
    const float* bout = (const float*)d_in[10];
    const float* ln1g = (const float*)d_in[11];
    const float* ln1b = (const float*)d_in[12];
    const float* w1   = (const float*)d_in[13];
    const float* b1   = (const float*)d_in[14];
    const float* w2   = (const float*)d_in[15];
    const float* b2   = (const float*)d_in[16];
    const float* ln2g = (const float*)d_in[17];
    const float* ln2b = (const float*)d_in[18];
    float* out = (float*)d_out;

    const int M = in_sizes[0] / CDIM;   // B*L = 26686

    float *value, *offp, *attnp, *accp, *src2, *xp, *hp, *yp;
    cudaGetSymbolAddress((void**)&value, g_value);
    cudaGetSymbolAddress((void**)&offp,  g_off);
    cudaGetSymbolAddress((void**)&attnp, g_attn);
    cudaGetSymbolAddress((void**)&accp,  g_acc);
    cudaGetSymbolAddress((void**)&src2,  g_src2);
    cudaGetSymbolAddress((void**)&xp,    g_x);
    cudaGetSymbolAddress((void**)&hp,    g_h);
    cudaGetSymbolAddress((void**)&yp,    g_y);

    // 1) value = src @ wv + bv
    gemm_kernel<false, false><<<gemm_grid(M, 256), 256>>>(src, nullptr, wv, bv, value, M, 256, 256);
    // 2) offsets = (src+pos) @ wo + bo
    gemm_kernel<true, false><<<gemm_grid(M, 320), 256>>>(src, pos, wo, bo, offp, M, 320, 256);
    // 3) attn logits = (src+pos) @ wa + ba
    gemm_kernel<true, false><<<gemm_grid(M, 160), 256>>>(src, pos, wa, ba, attnp, M, 160, 256);
    // 4) deformable sampling -> acc
    sample_kernel<<<M, 256>>>(value, ref, offp, attnp, accp);
    // 5) src2 = acc @ wout + bout
    gemm_kernel<false, false><<<gemm_grid(M, 256), 256>>>(accp, nullptr, wout, bout, src2, M, 256, 256);
    // 6) x = LN(src + src2)
    add_ln_kernel<<<(M + 7) / 8, 256>>>(src, src2, ln1g, ln1b, xp, M);
    // 7) h = relu(x @ w1 + b1)
    gemm_kernel<false, true><<<gemm_grid(M, 2048), 256>>>(xp, nullptr, w1, b1, hp, M, 2048, 256);
    // 8) y = h @ w2 + b2
    gemm_kernel<false, false><<<gemm_grid(M, 256), 256>>>(hp, nullptr, w2, b2, yp, M, 256, 2048);
    // 9) out = LN(x + y)
    add_ln_kernel<<<(M + 7) / 8, 256>>>(xp, yp, ln2g, ln2b, out, M);
}

// round 3
// speedup vs baseline: 2.5638x; 2.5638x over previous
#include <cuda_runtime.h>
#include <cstdint>

// ---------------- problem constants ----------------
#define L_Q   13343
#define BLMAX 26686          // B=2 * L_Q
#define CDIM  256

__constant__ int c_HW[5]    = {100, 50, 25, 13, 7};
__constant__ int c_start[5] = {0, 10000, 12500, 13125, 13294};

// ---------------- scratch (static device globals; no allocs) ----------------
__device__ float g_value[(size_t)BLMAX * 256];
__device__ float g_off  [(size_t)BLMAX * 320];
__device__ float g_attn [(size_t)BLMAX * 160];
__device__ float g_acc  [(size_t)BLMAX * 256];
__device__ float g_src2 [(size_t)BLMAX * 256];
__device__ float g_x    [(size_t)BLMAX * 256];
__device__ float g_h    [(size_t)BLMAX * 2048];
__device__ float g_y    [(size_t)BLMAX * 256];

// ---------------- tf32 helpers ----------------
__device__ __forceinline__ uint32_t f2tf32(float x) {
    uint32_t r;
    asm("cvt.rna.tf32.f32 %0, %1;" : "=r"(r) : "f"(x));
    return r;
}

__device__ __forceinline__ void mma_tf32(float* d, const uint32_t* a, const uint32_t* b) {
    asm volatile(
        "mma.sync.aligned.m16n8k8.row.col.f32.tf32.tf32.f32 "
        "{%0,%1,%2,%3}, {%4,%5,%6,%7}, {%8,%9}, {%0,%1,%2,%3};\n"
        : "+f"(d[0]), "+f"(d[1]), "+f"(d[2]), "+f"(d[3])
        : "r"(a[0]), "r"(a[1]), "r"(a[2]), "r"(a[3]), "r"(b[0]), "r"(b[1]));
}

// ---------------- TF32 tensor-core GEMM: C = act((A (+A2)) @ W + bias) ----------------
// Block tile 128x128, BK=16, 256 threads = 8 warps (2x4), warp tile 64x32,
// per warp 4x4 m16n8k8 tiles. Double-buffered smem, stride 136 words
// (=> 8c-bank groups, conflict-free fragment loads).
#define TBM 128
#define TBN 128
#define TBK 16
#define TPAD 8
#define TSTR (TBM + TPAD)

template<bool ADD_A, bool RELU>
__global__ __launch_bounds__(256, 2)
void gemm_tf32(const float* __restrict__ A, const float* __restrict__ A2,
               const float* __restrict__ W, const float* __restrict__ bias,
               float* __restrict__ C, int M, int N, int K)
{
    __shared__ uint32_t As[2][TBK][TSTR];
    __shared__ uint32_t Bs[2][TBK][TSTR];

    const int tid  = threadIdx.x;
    const int lane = tid & 31;
    const int warp = tid >> 5;
    const int wm = (warp >> 2) * 64;   // 0 / 64
    const int wn = (warp & 3) * 32;    // 0..96
    const int bm = blockIdx.y * TBM;
    const int bn = blockIdx.x * TBN;

    // loader indices: 2 float4 each for A tile (128x16) and W tile (16x128)
    int arow[2], acol[2], wrow[2], wcol[2];
    bool aval[2], wval[2];
    const float *Ap[2], *A2p[2], *Wp[2];
#pragma unroll
    for (int i = 0; i < 2; i++) {
        int f = tid * 2 + i;
        arow[i] = f >> 2;           acol[i] = (f & 3) * 4;
        wrow[i] = f >> 5;           wcol[i] = (f & 31) * 4;
        aval[i] = (bm + arow[i]) < M;
        wval[i] = (bn + wcol[i]) < N;
        Ap[i]  = A + (size_t)(bm + arow[i]) * K + acol[i];
        A2p[i] = ADD_A ? (A2 + (size_t)(bm + arow[i]) * K + acol[i]) : nullptr;
        Wp[i]  = W + (size_t)wrow[i] * N + bn + wcol[i];
    }

    float acc[4][4][4];
#pragma unroll
    for (int a = 0; a < 4; a++)
#pragma unroll
        for (int b = 0; b < 4; b++)
#pragma unroll
            for (int c = 0; c < 4; c++) acc[a][b][c] = 0.f;

    uint4 ar[2], wr[2];

    auto LDG = [&](int k0) {
#pragma unroll
        for (int i = 0; i < 2; i++) {
            float4 v = make_float4(0.f, 0.f, 0.f, 0.f);
            if (aval[i]) {
                v = *(const float4*)(Ap[i] + k0);
                if (ADD_A) {
                    float4 u = *(const float4*)(A2p[i] + k0);
                    v.x += u.x; v.y += u.y; v.z += u.z; v.w += u.w;
                }
            }
            ar[i].x = f2tf32(v.x); ar[i].y = f2tf32(v.y);
            ar[i].z = f2tf32(v.z); ar[i].w = f2tf32(v.w);
            float4 w4 = make_float4(0.f, 0.f, 0.f, 0.f);
            if (wval[i]) w4 = *(const float4*)(Wp[i] + (size_t)k0 * N);
            wr[i].x = f2tf32(w4.x); wr[i].y = f2tf32(w4.y);
            wr[i].z = f2tf32(w4.z); wr[i].w = f2tf32(w4.w);
        }
    };

    auto STS = [&](int s) {
#pragma unroll
        for (int i = 0; i < 2; i++) {
            As[s][acol[i] + 0][arow[i]] = ar[i].x;
            As[s][acol[i] + 1][arow[i]] = ar[i].y;
            As[s][acol[i] + 2][arow[i]] = ar[i].z;
            As[s][acol[i] + 3][arow[i]] = ar[i].w;
            *(uint4*)&Bs[s][wrow[i]][wcol[i]] = wr[i];
        }
    };

    auto COMPUTE = [&](int s) {
        const int r = lane >> 2, c = lane & 3;
#pragma unroll
        for (int kc = 0; kc < TBK; kc += 8) {
            uint32_t af[4][4], bf[4][2];
#pragma unroll
            for (int mt = 0; mt < 4; mt++) {
                int rr = wm + mt * 16 + r;
                af[mt][0] = As[s][kc + c][rr];
                af[mt][1] = As[s][kc + c][rr + 8];
                af[mt][2] = As[s][kc + c + 4][rr];
                af[mt][3] = As[s][kc + c + 4][rr + 8];
            }
#pragma unroll
            for (int nt = 0; nt < 4; nt++) {
                int cc = wn + nt * 8 + r;
                bf[nt][0] = Bs[s][kc + c][cc];
                bf[nt][1] = Bs[s][kc + c + 4][cc];
            }
#pragma unroll
            for (int mt = 0; mt < 4; mt++)
#pragma unroll
                for (int nt = 0; nt < 4; nt++)
                    mma_tf32(acc[mt][nt], af[mt], bf[nt]);
        }
    };

    LDG(0); STS(0); __syncthreads();
    int s = 0;
    for (int k0 = TBK; k0 < K + TBK; k0 += TBK) {
        const bool more = (k0 < K);
        if (more) LDG(k0);
        COMPUTE(s);
        if (more) {
            STS(s ^ 1);
            __syncthreads();
            s ^= 1;
        }
    }

    // epilogue
    const int r = lane >> 2, c2 = (lane & 3) * 2;
#pragma unroll
    for (int mt = 0; mt < 4; mt++) {
        const int r0 = bm + wm + mt * 16 + r;
#pragma unroll
        for (int nt = 0; nt < 4; nt++) {
            const int cc = bn + wn + nt * 8 + c2;
            if (cc < N) {
                const float b0 = bias[cc], b1 = bias[cc + 1];
                if (r0 < M) {
                    float2 o;
                    o.x = acc[mt][nt][0] + b0;
                    o.y = acc[mt][nt][1] + b1;
                    if (RELU) { o.x = fmaxf(o.x, 0.f); o.y = fmaxf(o.y, 0.f); }
                    *(float2*)&C[(size_t)r0 * N + cc] = o;
                }
                if (r0 + 8 < M) {
                    float2 o;
                    o.x = acc[mt][nt][2] + b0;
                    o.y = acc[mt][nt][3] + b1;
                    if (RELU) { o.x = fmaxf(o.x, 0.f); o.y = fmaxf(o.y, 0.f); }
                    *(float2*)&C[(size_t)(r0 + 8) * N + cc] = o;
                }
            }
        }
    }
}

// ---------------- deformable sampling ----------------
// One block (64 threads) per query. Thread = (head h = t>>3, channel group (t&7)*4).
// Each corner gather is a float4; 8 lanes per head cover 128B contiguous.
__global__ __launch_bounds__(64)
void sample_kernel(const float* __restrict__ value,   // [B, L, 256]
                   const float* __restrict__ ref,     // [B, L, 5, 2]
                   const float* __restrict__ off,     // [B*L, 320]
                   const float* __restrict__ logits,  // [B*L, 160]
                   float* __restrict__ acc_out)       // [B*L, 256]
{
    const int q = blockIdx.x;
    const int b = q / L_Q;
    const int t = threadIdx.x;

    __shared__ float s_off[320];
    __shared__ float s_log[160];
    __shared__ float s_ref[10];

#pragma unroll
    for (int i = t; i < 320; i += 64) s_off[i] = off[(size_t)q * 320 + i];
#pragma unroll
    for (int i = t; i < 160; i += 64) s_log[i] = logits[(size_t)q * 160 + i];
    if (t < 10) s_ref[t] = ref[(size_t)q * 10 + t];
    __syncthreads();

    const int h  = t >> 3;
    const int ci = (t & 7) * 4;

    // single-pass softmax over this head's 20 logits
    float m = -1e30f;
#pragma unroll
    for (int p = 0; p < 20; p++) m = fmaxf(m, s_log[h * 20 + p]);
    float e[20], ssum = 0.f;
#pragma unroll
    for (int p = 0; p < 20; p++) { e[p] = __expf(s_log[h * 20 + p] - m); ssum += e[p]; }
    const float inv = 1.0f / ssum;

    float4 a = make_float4(0.f, 0.f, 0.f, 0.f);
    const float* vbase = value + (size_t)b * L_Q * 256 + h * 32 + ci;

#pragma unroll
    for (int l = 0; l < 5; l++) {
        const int Hs = c_HW[l], Ws = c_HW[l];
        const float* vlvl = vbase + (size_t)c_start[l] * 256;
        const float rx = s_ref[l * 2 + 0];
        const float ry = s_ref[l * 2 + 1];
#pragma unroll
        for (int p = 0; p < 4; p++) {
            const float ox = s_off[h * 40 + l * 8 + p * 2 + 0];
            const float oy = s_off[h * 40 + l * 8 + p * 2 + 1];
            const float w  = e[l * 4 + p] * inv;

            const float locx = rx + ox / (float)Ws;
            const float locy = ry + oy / (float)Hs;
            const float px = locx * (float)Ws - 0.5f;
            const float py = locy * (float)Hs - 0.5f;

            const float x0f = floorf(px), y0f = floorf(py);
            const float lx = px - x0f, ly = py - y0f;
            const int x0 = (int)x0f, y0 = (int)y0f;
            const int x1 = x0 + 1,  y1 = y0 + 1;

            const bool vx0 = (x0 >= 0) & (x0 < Ws);
            const bool vx1 = (x1 >= 0) & (x1 < Ws);
            const bool vy0 = (y0 >= 0) & (y0 < Hs);
            const bool vy1 = (y1 >= 0) & (y1 < Hs);

            if (vx0 & vy0) {
                const float cw = w * (1.f - lx) * (1.f - ly);
                float4 v = *(const float4*)(vlvl + (size_t)(y0 * Ws + x0) * 256);
                a.x = fmaf(cw, v.x, a.x); a.y = fmaf(cw, v.y, a.y);
                a.z = fmaf(cw, v.z, a.z); a.w = fmaf(cw, v.w, a.w);
            }
            if (vx1 & vy0) {
                const float cw = w * lx * (1.f - ly);
                float4 v = *(const float4*)(vlvl + (size_t)(y0 * Ws + x1) * 256);
                a.x = fmaf(cw, v.x, a.x); a.y = fmaf(cw, v.y, a.y);
                a.z = fmaf(cw, v.z, a.z); a.w = fmaf(cw, v.w, a.w);
            }
            if (vx0 & vy1) {
                const float cw = w * (1.f - lx) * ly;
                float4 v = *(const float4*)(vlvl + (size_t)(y1 * Ws + x0) * 256);
                a.x = fmaf(cw, v.x, a.x); a.y = fmaf(cw, v.y, a.y);
                a.z = fmaf(cw, v.z, a.z); a.w = fmaf(cw, v.w, a.w);
            }
            if (vx1 & vy1) {
                const float cw = w * lx * ly;
                float4 v = *(const float4*)(vlvl + (size_t)(y1 * Ws + x1) * 256);
                a.x = fmaf(cw, v.x, a.x); a.y = fmaf(cw, v.y, a.y);
                a.z = fmaf(cw, v.z, a.z); a.w = fmaf(cw, v.w, a.w);
            }
        }
    }
    *(float4*)&acc_out[(size_t)q * 256 + h * 32 + ci] = a;
}

// ---------------- fused add + layernorm: out = LN(a+b)*g + beta ----------------
__global__ __launch_bounds__(256)
void add_ln_kernel(const float* __restrict__ a, const float* __restrict__ b,
                   const float* __restrict__ g, const float* __restrict__ be,
                   float* __restrict__ out, int M)
{
    const int warp = threadIdx.x >> 5;
    const int lane = threadIdx.x & 31;
    const int row  = blockIdx.x * 8 + warp;
    if (row >= M) return;

    const float* ar = a + (size_t)row * 256;
    const float* br = b + (size_t)row * 256;

    float4 v0 = *(const float4*)(ar + lane * 4);
    float4 v1 = *(const float4*)(ar + 128 + lane * 4);
    float4 w0 = *(const float4*)(br + lane * 4);
    float4 w1 = *(const float4*)(br + 128 + lane * 4);

    float v[8];
    v[0] = v0.x + w0.x; v[1] = v0.y + w0.y; v[2] = v0.z + w0.z; v[3] = v0.w + w0.w;
    v[4] = v1.x + w1.x; v[5] = v1.y + w1.y; v[6] = v1.z + w1.z; v[7] = v1.w + w1.w;

    float s = 0.f, sq = 0.f;
#pragma unroll
    for (int i = 0; i < 8; i++) { s += v[i]; sq = fmaf(v[i], v[i], sq); }
#pragma unroll
    for (int o = 16; o; o >>= 1) {
        s  += __shfl_xor_sync(0xffffffffu, s,  o);
        sq += __shfl_xor_sync(0xffffffffu, sq, o);
    }
    const float mean = s * (1.f / 256.f);
    const float var  = sq * (1.f / 256.f) - mean * mean;
    const float inv  = rsqrtf(var + 1e-5f);

    float* orow = out + (size_t)row * 256;
#pragma unroll
    for (int half = 0; half < 2; half++) {
        int c = half * 128 + lane * 4;
        float4 o;
        float* vv = v + half * 4;
        o.x = (vv[0] - mean) * inv * g[c + 0] + be[c + 0];
        o.y = (vv[1] - mean) * inv * g[c + 1] + be[c + 1];
        o.z = (vv[2] - mean) * inv * g[c + 2] + be[c + 2];
        o.w = (vv[3] - mean) * inv * g[c + 3] + be[c + 3];
        *(float4*)&orow[c] = o;
    }
}

// ---------------- launch ----------------
static inline dim3 tgrid(int M, int N) {
    return dim3((N + TBN - 1) / TBN, (M + TBM - 1) / TBM);
}

extern "C" void kernel_launch(void* const* d_in, const int* in_sizes, int n_in,
                              void* d_out, int out_size)
{
    const float* src  = (const float*)d_in[0];
    const float* pos  = (const float*)d_in[1];
    const float* ref  = (const float*)d_in[2];
    const float* wv   = (const float*)d_in[3];
    const float* bv   = (const float*)d_in[4];
    const float* wo   = (const float*)d_in[5];
    const float* bo   = (const float*)d_in[6];
    const float* wa   = (const float*)d_in[7];
    const float* ba   = (const float*)d_in[8];
    const float* wout = (const float*)d_in[9];
    const float* bout = (const float*)d_in[10];
    const float* ln1g = (const float*)d_in[11];
    const float* ln1b = (const float*)d_in[12];
    const float* w1   = (const float*)d_in[13];
    const float* b1   = (const float*)d_in[14];
    const float* w2   = (const float*)d_in[15];
    const float* b2   = (const float*)d_in[16];
    const float* ln2g = (const float*)d_in[17];
    const float* ln2b = (const float*)d_in[18];
    float* out = (float*)d_out;

    const int M = in_sizes[0] / CDIM;   // B*L = 26686

    float *value, *offp, *attnp, *accp, *src2, *xp, *hp, *yp;
    cudaGetSymbolAddress((void**)&value, g_value);
    cudaGetSymbolAddress((void**)&offp,  g_off);
    cudaGetSymbolAddress((void**)&attnp, g_attn);
    cudaGetSymbolAddress((void**)&accp,  g_acc);
    cudaGetSymbolAddress((void**)&src2,  g_src2);
    cudaGetSymbolAddress((void**)&xp,    g_x);
    cudaGetSymbolAddress((void**)&hp,    g_h);
    cudaGetSymbolAddress((void**)&yp,    g_y);

    // 1) value = src @ wv + bv
    gemm_tf32<false, false><<<tgrid(M, 256), 256>>>(src, nullptr, wv, bv, value, M, 256, 256);
    // 2) offsets = (src+pos) @ wo + bo
    gemm_tf32<true, false><<<tgrid(M, 320), 256>>>(src, pos, wo, bo, offp, M, 320, 256);
    // 3) attn logits = (src+pos) @ wa + ba
    gemm_tf32<true, false><<<tgrid(M, 160), 256>>>(src, pos, wa, ba, attnp, M, 160, 256);
    // 4) deformable sampling -> acc
    sample_kernel<<<M, 64>>>(value, ref, offp, attnp, accp);
    // 5) src2 = acc @ wout + bout
    gemm_tf32<false, false><<<tgrid(M, 256), 256>>>(accp, nullptr, wout, bout, src2, M, 256, 256);
    // 6) x = LN(src + src2)
    add_ln_kernel<<<(M + 7) / 8, 256>>>(src, src2, ln1g, ln1b, xp, M);
    // 7) h = relu(x @ w1 + b1)
    gemm_tf32<false, true><<<tgrid(M, 2048), 256>>>(xp, nullptr, w1, b1, hp, M, 2048, 256);
    // 8) y = h @ w2 + b2
    gemm_tf32<false, false><<<tgrid(M, 256), 256>>>(hp, nullptr, w2, b2, yp, M, 256, 2048);
    // 9) out = LN(x + y)
    add_ln_kernel<<<(M + 7) / 8, 256>>>(xp, yp, ln2g, ln2b, out, M);
}